// round 6
// baseline (speedup 1.0000x reference)
#include <cuda_runtime.h>
#include <cuda_bf16.h>

#define OUT_SZ 7
#define NCELL (OUT_SZ * OUT_SZ)      // 49
#define NCH 256
#define NQ (NCH / 4)                 // 64 float4 per channel row
#define MAX_ROIS 1024

struct alignas(32) RoiP {
    float y_base, x_base, h_scale, w_scale;
    float Hm1;                 // H-1 == W-1
    int   W;
    const float4* fm_b;        // resolved base (batch+level)
};

__device__ RoiP g_params[MAX_ROIS];

__global__ void decode_kernel(const float* __restrict__ p2,
                              const float* __restrict__ p3,
                              const float* __restrict__ p4,
                              const float* __restrict__ p5,
                              const float* __restrict__ rois,
                              int n_rois)
{
    int roi = blockIdx.x * blockDim.x + threadIdx.x;
    if (roi >= n_rois) return;

    // rois row: [batch, x1, y1, x2, y2]
    const float* r = rois + (size_t)roi * 5;
    float bf  = __ldg(r + 0);
    float rx1 = __ldg(r + 1), ry1 = __ldg(r + 2);
    float rx2 = __ldg(r + 3), ry2 = __ldg(r + 4);
    int b = (int)bf;

    float roi_w = rx2 - rx1;
    float roi_h = ry2 - ry1;
    float lvl = 4.0f + log2f(sqrtf(roi_h * roi_w) / 224.0f);
    int level = (int)rintf(lvl);
    level = level < 2 ? 2 : (level > 5 ? 5 : level);

    const float* fm;
    int H;
    float inv_stride;
    switch (level) {
        case 2: fm = p2; H = 256; inv_stride = 1.0f / 4.0f;  break;
        case 3: fm = p3; H = 128; inv_stride = 1.0f / 8.0f;  break;
        case 4: fm = p4; H = 64;  inv_stride = 1.0f / 16.0f; break;
        default: fm = p5; H = 32; inv_stride = 1.0f / 32.0f; break;
    }
    float Hm1 = (float)(H - 1);

    // crop_and_resize reads boxes as [y1,x1,y2,x2]; roi_align passes
    // [x1,y1,x2,y2]*(1/stride). So box_y1 = rx1/stride, box_x1 = ry1/stride.
    float by1 = rx1 * inv_stride;
    float bx1 = ry1 * inv_stride;
    float by2 = rx2 * inv_stride;
    float bx2 = ry2 * inv_stride;

    RoiP p;
    p.h_scale = (by2 - by1) * Hm1 * (1.0f / (float)(OUT_SZ - 1));
    p.w_scale = (bx2 - bx1) * Hm1 * (1.0f / (float)(OUT_SZ - 1));
    p.y_base  = by1 * Hm1;
    p.x_base  = bx1 * Hm1;
    p.Hm1     = Hm1;
    p.W       = H;
    p.fm_b    = (const float4*)(fm + (size_t)b * H * H * NCH);
    g_params[roi] = p;
}

__device__ __forceinline__ float4 lerp2d(float4 tl, float4 tr, float4 bl, float4 br,
                                         float lx, float ly)
{
    float4 top, bot, v;
    top.x = fmaf(tr.x - tl.x, lx, tl.x);
    top.y = fmaf(tr.y - tl.y, lx, tl.y);
    top.z = fmaf(tr.z - tl.z, lx, tl.z);
    top.w = fmaf(tr.w - tl.w, lx, tl.w);
    bot.x = fmaf(br.x - bl.x, lx, bl.x);
    bot.y = fmaf(br.y - bl.y, lx, bl.y);
    bot.z = fmaf(br.z - bl.z, lx, bl.z);
    bot.w = fmaf(br.w - bl.w, lx, bl.w);
    v.x = fmaf(bot.x - top.x, ly, top.x);
    v.y = fmaf(bot.y - top.y, ly, top.y);
    v.z = fmaf(bot.z - top.z, ly, top.z);
    v.w = fmaf(bot.w - top.w, ly, top.w);
    return v;
}

// grid (n_rois, 7): blockIdx.y = output row i.
// 256 threads: cq = tid&63 channel quad, slot = tid>>6 handles columns slot and slot+4.
__global__ __launch_bounds__(256, 6)
void gather_kernel(float* __restrict__ out)
{
    int roi  = blockIdx.x;
    int tid  = threadIdx.x;
    int cq   = tid & (NQ - 1);
    int slot = tid >> 6;             // 0..3
    int i    = blockIdx.y;           // row 0..6
    int j0   = slot;
    int j1   = slot + 4;             // 4..7 (7 masked)

    RoiP p = g_params[roi];
    float Hm1 = p.Hm1;
    int   W   = p.W;

    // y axis (shared by both cells)
    float in_y = fmaf((float)i, p.h_scale, p.y_base);
    bool  vy   = (in_y >= 0.0f) & (in_y <= Hm1);
    float fy   = floorf(in_y);
    float ly   = in_y - fy;
    int   y0   = (int)fmaxf(fy, 0.0f);          // safe even if invalid
    int   yc   = (int)fminf(fmaxf(ceilf(in_y), 0.0f), Hm1);
    y0 = y0 > (int)Hm1 ? (int)Hm1 : y0;

    const float4* row0 = p.fm_b + (size_t)y0 * W * NQ;
    const float4* row1 = p.fm_b + (size_t)yc * W * NQ;

    // x axis for both cells
    float in_x0 = fmaf((float)j0, p.w_scale, p.x_base);
    float in_x1 = fmaf((float)j1, p.w_scale, p.x_base);
    bool  vx0 = (in_x0 >= 0.0f) & (in_x0 <= Hm1);
    bool  vx1 = (in_x1 >= 0.0f) & (in_x1 <= Hm1) & (j1 < OUT_SZ);
    float fx0 = floorf(in_x0), fx1 = floorf(in_x1);
    float lx0 = in_x0 - fx0,  lx1 = in_x1 - fx1;
    int x00 = min(max((int)fx0, 0), (int)Hm1);
    int x0c = (int)fminf(fmaxf(ceilf(in_x0), 0.0f), Hm1);
    int x10 = min(max((int)fx1, 0), (int)Hm1);
    int x1c = (int)fminf(fmaxf(ceilf(in_x1), 0.0f), Hm1);

    // Issue all 8 gathers (clamped addresses are always safe; results masked).
    float4 a_tl = __ldg(row0 + x00 * NQ + cq);
    float4 a_tr = __ldg(row0 + x0c * NQ + cq);
    float4 a_bl = __ldg(row1 + x00 * NQ + cq);
    float4 a_br = __ldg(row1 + x0c * NQ + cq);
    float4 b_tl = __ldg(row0 + x10 * NQ + cq);
    float4 b_tr = __ldg(row0 + x1c * NQ + cq);
    float4 b_bl = __ldg(row1 + x10 * NQ + cq);
    float4 b_br = __ldg(row1 + x1c * NQ + cq);

    float4 zero = make_float4(0.f, 0.f, 0.f, 0.f);
    float4 va = (vy & vx0) ? lerp2d(a_tl, a_tr, a_bl, a_br, lx0, ly) : zero;

    float4* out_base = (float4*)(out + (size_t)roi * NCELL * NCH) + i * OUT_SZ * NQ;
    out_base[j0 * NQ + cq] = va;

    if (j1 < OUT_SZ) {
        float4 vb = (vy & vx1) ? lerp2d(b_tl, b_tr, b_bl, b_br, lx1, ly) : zero;
        out_base[j1 * NQ + cq] = vb;
    }
}

extern "C" void kernel_launch(void* const* d_in, const int* in_sizes, int n_in,
                              void* d_out, int out_size)
{
    const float* p2   = (const float*)d_in[0];
    const float* p3   = (const float*)d_in[1];
    const float* p4   = (const float*)d_in[2];
    const float* p5   = (const float*)d_in[3];
    const float* rois = (const float*)d_in[4];
    float* out = (float*)d_out;
    int n_rois = in_sizes[4] / 5;

    int dec_threads = 128;
    int dec_blocks = (n_rois + dec_threads - 1) / dec_threads;
    decode_kernel<<<dec_blocks, dec_threads>>>(p2, p3, p4, p5, rois, n_rois);

    dim3 grid(n_rois, OUT_SZ);
    gather_kernel<<<grid, 256>>>(out);
}